// round 14
// baseline (speedup 1.0000x reference)
#include <cuda_runtime.h>
#include <stdint.h>

// Shapes (fixed by the problem)
#define BATCH 32
#define SEQ   4096
#define VOCAB 10
#define FEAT  1024
#define DIM   64

#define CHUNK   256
#define THREADS 256
#define NPRODC  64                          // producer CTAs (one per d)
#define NCONS   (BATCH * (SEQ / CHUNK))     // 512 consumer CTAs
#define NCTAS   (NPRODC + NCONS)            // 576
#define NGRP    16                          // d-groups of 4 rows

// Projected table P[d][v] + per-group ready counters (memset each launch)
__device__ float    g_P[DIM * VOCAB];
__device__ unsigned g_grp[NGRP];

__device__ __forceinline__ unsigned ld_acquire(const unsigned* p) {
    unsigned v;
    asm volatile("ld.acquire.gpu.global.u32 %0, [%1];" : "=r"(v) : "l"(p));
    return v;
}

// One warp computes one (d,v) dot: 16 independent LDG.128, shfl reduce.
__device__ __forceinline__ float dot_dv(int d, int v, int lane,
                                        const float* __restrict__ fp,
                                        const float* __restrict__ W) {
    const float4* fr = reinterpret_cast<const float4*>(fp + v * FEAT);
    const float4* wr = reinterpret_cast<const float4*>(W  + d * FEAT);
    float s = 0.f;
#pragma unroll
    for (int f = lane; f < FEAT / 4; f += 32) {
        float4 a = fr[f];
        float4 c = wr[f];
        s += a.x * c.x + a.y * c.y + a.z * c.z + a.w * c.w;
    }
#pragma unroll
    for (int o = 16; o > 0; o >>= 1)
        s += __shfl_down_sync(0xffffffffu, s, o);
    return s;
}

// ---------------------------------------------------------------------------
// Single fused kernel, pipelined at d-group granularity.
//   CTAs [0,64):    producer for d = bid: 10 dots (warps 0..7; warps 0/1
//                   take v=8,9 as a second round), publish, count group.
//   CTAs [64,576):  consumer: prefetch indices, then per k-iteration wait
//                   only for group k (per-warp lane0 acquire-poll), read the
//                   4 P rows from L2, store. Store stream starts as soon as
//                   group 0 is ready (~0.7us), not after all of P.
// ---------------------------------------------------------------------------
__global__ void __launch_bounds__(THREADS)
fused_kernel(const int* __restrict__ idx,
             const float* __restrict__ fp,
             const float* __restrict__ W,
             const float* __restrict__ bias,
             float* __restrict__ out) {
    const int tid  = threadIdx.x;
    const int bid  = blockIdx.x;
    const int wid  = tid >> 5;
    const int lane = tid & 31;

    if (bid < NPRODC) {
        // ----- producer: P[d][0..9] for d = bid -----
        const int d = bid;
        float s0 = dot_dv(d, wid, lane, fp, W);
        if (lane == 0) g_P[d * VOCAB + wid] = s0 + bias[d];
        if (wid < 2) {                        // v = 8, 9
            float s1 = dot_dv(d, 8 + wid, lane, fp, W);
            if (lane == 0) g_P[d * VOCAB + 8 + wid] = s1 + bias[d];
        }
        __syncthreads();
        if (tid == 0) {
            __threadfence();                  // publish row d to L2
            atomicAdd(&g_grp[d >> 2], 1u);    // 4 arrivals per group counter
        }
        return;
    }

    // ----- consumer: one (b, 256-token) chunk -----
    const int cid = bid - NPRODC;             // 0..511
    const int b   = cid >> 4;                 // 16 chunks per batch row
    const int l0  = (cid & 15) * CHUNK;
    const int lq  = tid & 63;                 // float4 slot (fixed per thread)
    const int db  = tid >> 6;                 // base d-row (0..3)

    // P-independent prefetch: this thread's 4 vocab indices (coalesced 16B)
    int4 iv = *reinterpret_cast<const int4*>(idx + b * SEQ + l0 + lq * 4);

    float* ob = out + (b * DIM) * SEQ + l0 + lq * 4;

#pragma unroll
    for (int k = 0; k < NGRP; k++) {
        // Per-warp wait: group k (d in [4k, 4k+4)) must be published
        if (lane == 0) {
            while (ld_acquire(&g_grp[k]) < 4u) __nanosleep(32);
        }
        __syncwarp();

        const int d = db + 4 * k;
        const float* p = &g_P[d * VOCAB];     // L2-hot row (first touch here)
        float4 r;
        r.x = __ldg(p + iv.x);
        r.y = __ldg(p + iv.y);
        r.z = __ldg(p + iv.z);
        r.w = __ldg(p + iv.w);
        *reinterpret_cast<float4*>(ob + d * SEQ) = r;
    }
}

// ---------------------------------------------------------------------------
// Graph per launch: [memset g_grp = 0] -> [fused_kernel]. Capture-legal,
// deterministic across replays (R13 validated the memset-node pattern).
// Inputs per metadata order: indices (int32), fp_table (f32), W (f32), b (f32)
// ---------------------------------------------------------------------------
extern "C" void kernel_launch(void* const* d_in, const int* in_sizes, int n_in,
                              void* d_out, int out_size) {
    const int*   idx  = (const int*)d_in[0];
    const float* fp   = (const float*)d_in[1];
    const float* W    = (const float*)d_in[2];
    const float* bias = (const float*)d_in[3];
    float*       out  = (float*)d_out;

    void* grp_addr = nullptr;
    cudaGetSymbolAddress(&grp_addr, g_grp);
    cudaMemsetAsync(grp_addr, 0, NGRP * sizeof(unsigned), 0);

    fused_kernel<<<NCTAS, THREADS>>>(idx, fp, W, bias, out);
}

// round 15
// speedup vs baseline: 2.3366x; 2.3366x over previous
#include <cuda_runtime.h>
#include <stdint.h>

// Shapes (fixed by the problem)
#define BATCH 32
#define SEQ   4096
#define VOCAB 10
#define FEAT  1024
#define DIM   64

#define CHUNK   256
#define THREADS 256

// Precomputed projected table: P[d][v] = b[d] + sum_f fp[v][f] * W[d][f]
__device__ float g_P[DIM * VOCAB];

// ---------------------------------------------------------------------------
// Kernel 1: tiny 10x64x1024 GEMM. One warp per (d, v) pair -> 640 warps.
// Triggers PDL completion once g_P is published.
// ---------------------------------------------------------------------------
__global__ void compute_P_kernel(const float* __restrict__ fp,
                                 const float* __restrict__ W,
                                 const float* __restrict__ bias) {
    int w    = (blockIdx.x * blockDim.x + threadIdx.x) >> 5;
    int lane = threadIdx.x & 31;
    int d = w / VOCAB;
    int v = w - d * VOCAB;

    const float4* fr = reinterpret_cast<const float4*>(fp + v * FEAT);
    const float4* wr = reinterpret_cast<const float4*>(W  + d * FEAT);

    float s = 0.f;
#pragma unroll
    for (int f = lane; f < FEAT / 4; f += 32) {
        float4 a = fr[f];
        float4 c = wr[f];
        s += a.x * c.x + a.y * c.y + a.z * c.z + a.w * c.w;
    }

#pragma unroll
    for (int o = 16; o > 0; o >>= 1)
        s += __shfl_down_sync(0xffffffffu, s, o);

    if (lane == 0)
        g_P[d * VOCAB + v] = s + bias[d];

    __threadfence();
    cudaTriggerProgrammaticLaunchCompletion();
}

// ---------------------------------------------------------------------------
// Kernel 2: gather. out[(b*DIM + d)*SEQ + l] = P[d][idx[b][l]]
// Exactly the R3 loop (best measured gather: 9.95us) + PDL dependency wait.
// __launch_bounds__(256,4): 4 CTAs/SM residency hint that accompanied the
// fastest measured variant.
// ---------------------------------------------------------------------------
__global__ void __launch_bounds__(THREADS, 4)
gather_kernel(const int* __restrict__ idx, float* __restrict__ out) {
    __shared__ float sP[DIM * VOCAB];

    const int b   = blockIdx.y;
    const int l0  = blockIdx.x * CHUNK;
    const int tid = threadIdx.x;
    const int lq  = tid & 63;            // float4 slot within chunk (fixed)
    const int db  = tid >> 6;            // base d-row (0..3)

    // P-independent prelude: this thread's 4 vocab indices (coalesced 16B)
    int4 iv = *reinterpret_cast<const int4*>(idx + b * SEQ + l0 + lq * 4);

    // HW wait for compute_P_kernel (no spin)
    cudaGridDependencySynchronize();

    // Projected table into shared: [d][v]
    for (int i = tid; i < DIM * VOCAB; i += THREADS)
        sP[i] = g_P[i];
    __syncthreads();

    float* ob = out + (b * DIM) * SEQ + l0 + lq * 4;

#pragma unroll
    for (int k = 0; k < 16; k++) {
        const int d = db + 4 * k;
        const float* p = &sP[d * VOCAB];
        float4 r;
        r.x = p[iv.x];
        r.y = p[iv.y];
        r.z = p[iv.z];
        r.w = p[iv.w];
        *reinterpret_cast<float4*>(ob + d * SEQ) = r;
    }
}

// ---------------------------------------------------------------------------
// Inputs per metadata order: indices (int32), fp_table (f32), W (f32), b (f32)
// ---------------------------------------------------------------------------
extern "C" void kernel_launch(void* const* d_in, const int* in_sizes, int n_in,
                              void* d_out, int out_size) {
    const int*   idx  = (const int*)d_in[0];
    const float* fp   = (const float*)d_in[1];
    const float* W    = (const float*)d_in[2];
    const float* bias = (const float*)d_in[3];
    float*       out  = (float*)d_out;

    compute_P_kernel<<<80, 256>>>(fp, W, bias);

    cudaLaunchConfig_t cfg = {};
    cfg.gridDim          = dim3(SEQ / CHUNK, BATCH);   // (16, 32) = 512 CTAs
    cfg.blockDim         = dim3(THREADS, 1, 1);
    cfg.dynamicSmemBytes = 0;
    cfg.stream           = 0;

    cudaLaunchAttribute attr[1];
    attr[0].id = cudaLaunchAttributeProgrammaticStreamSerialization;
    attr[0].val.programmaticStreamSerializationAllowed = 1;
    cfg.attrs    = attr;
    cfg.numAttrs = 1;

    cudaLaunchKernelEx(&cfg, gather_kernel, idx, out);
}

// round 16
// speedup vs baseline: 2.3835x; 1.0201x over previous
#include <cuda_runtime.h>
#include <stdint.h>

// Shapes (fixed by the problem)
#define BATCH 32
#define SEQ   4096
#define VOCAB 10
#define FEAT  1024
#define DIM   64

#define CHUNK   256
#define THREADS 256

// Precomputed projected table: P[d][v] = b[d] + sum_f fp[v][f] * W[d][f]
__device__ float g_P[DIM * VOCAB];

// ---------------------------------------------------------------------------
// Kernel 1: tiny 10x64x1024 GEMM. One warp per (d, v) pair -> 640 warps.
// ---------------------------------------------------------------------------
__global__ void compute_P_kernel(const float* __restrict__ fp,
                                 const float* __restrict__ W,
                                 const float* __restrict__ bias) {
    int w    = (blockIdx.x * blockDim.x + threadIdx.x) >> 5;
    int lane = threadIdx.x & 31;
    int d = w / VOCAB;
    int v = w - d * VOCAB;

    const float4* fr = reinterpret_cast<const float4*>(fp + v * FEAT);
    const float4* wr = reinterpret_cast<const float4*>(W  + d * FEAT);

    float s = 0.f;
#pragma unroll
    for (int f = lane; f < FEAT / 4; f += 32) {
        float4 a = fr[f];
        float4 c = wr[f];
        s += a.x * c.x + a.y * c.y + a.z * c.z + a.w * c.w;
    }

#pragma unroll
    for (int o = 16; o > 0; o >>= 1)
        s += __shfl_down_sync(0xffffffffu, s, o);

    if (lane == 0)
        g_P[d * VOCAB + v] = s + bias[d];

    __threadfence();
    cudaTriggerProgrammaticLaunchCompletion();
}

// ---------------------------------------------------------------------------
// Kernel 2: gather with STREAMING stores (st.global.cs.v4.f32).
// The 33.5 MB output is write-once, never re-read in-kernel: evict-first
// policy relieves L2 write-allocation pressure if that is the serializer.
// Loop otherwise identical to the proven 12.768 config.
// ---------------------------------------------------------------------------
__global__ void __launch_bounds__(THREADS)
gather_kernel(const int* __restrict__ idx, float* __restrict__ out) {
    __shared__ float sP[DIM * VOCAB];

    const int b   = blockIdx.y;
    const int l0  = blockIdx.x * CHUNK;
    const int tid = threadIdx.x;
    const int lq  = tid & 63;            // float4 slot within chunk (fixed)
    const int db  = tid >> 6;            // base d-row (0..3)

    // P-independent prelude: this thread's 4 vocab indices (coalesced 16B)
    int4 iv = *reinterpret_cast<const int4*>(idx + b * SEQ + l0 + lq * 4);

    // HW wait for compute_P_kernel (no spin)
    cudaGridDependencySynchronize();

    // Projected table into shared: [d][v]
    for (int i = tid; i < DIM * VOCAB; i += THREADS)
        sP[i] = g_P[i];
    __syncthreads();

    float* ob = out + (b * DIM) * SEQ + l0 + lq * 4;

#pragma unroll
    for (int k = 0; k < 16; k++) {
        const int d = db + 4 * k;
        const float* p = &sP[d * VOCAB];

        float r0 = p[iv.x];
        float r1 = p[iv.y];
        float r2 = p[iv.z];
        float r3 = p[iv.w];

        asm volatile(
            "st.global.cs.v4.f32 [%0], {%1,%2,%3,%4};"
            :: "l"(ob + d * SEQ), "f"(r0), "f"(r1), "f"(r2), "f"(r3)
            : "memory");
    }
}

// ---------------------------------------------------------------------------
// Inputs per metadata order: indices (int32), fp_table (f32), W (f32), b (f32)
// ---------------------------------------------------------------------------
extern "C" void kernel_launch(void* const* d_in, const int* in_sizes, int n_in,
                              void* d_out, int out_size) {
    const int*   idx  = (const int*)d_in[0];
    const float* fp   = (const float*)d_in[1];
    const float* W    = (const float*)d_in[2];
    const float* bias = (const float*)d_in[3];
    float*       out  = (float*)d_out;

    compute_P_kernel<<<80, 256>>>(fp, W, bias);

    cudaLaunchConfig_t cfg = {};
    cfg.gridDim          = dim3(SEQ / CHUNK, BATCH);   // (16, 32) = 512 CTAs
    cfg.blockDim         = dim3(THREADS, 1, 1);
    cfg.dynamicSmemBytes = 0;
    cfg.stream           = 0;

    cudaLaunchAttribute attr[1];
    attr[0].id = cudaLaunchAttributeProgrammaticStreamSerialization;
    attr[0].val.programmaticStreamSerializationAllowed = 1;
    cfg.attrs    = attr;
    cfg.numAttrs = 1;

    cudaLaunchKernelEx(&cfg, gather_kernel, idx, out);
}